// round 4
// baseline (speedup 1.0000x reference)
#include <cuda_runtime.h>
#include <math_constants.h>

#define BS   8192
#define D    128
#define TILE 128
#define KC   32

// Scratch (allocation-free rule: __device__ globals)
__device__ float        g_a_sq[BS];
__device__ float        g_p_sq[BS];
__device__ float        g_pos_d2[BS];
__device__ unsigned int g_neg_bits[BS];

// ---------------------------------------------------------------------------
// Kernel 1: per-row squared norms, pos squared distance, init neg-min to +inf
// ---------------------------------------------------------------------------
__global__ void prep_kernel(const float* __restrict__ feats) {
    int row = blockIdx.x * blockDim.x + threadIdx.x;
    if (row >= BS) return;
    const float4* a = (const float4*)(feats + (size_t)row * D);
    const float4* p = (const float4*)(feats + (size_t)(BS + row) * D);
    float asq = 0.f, psq = 0.f, pd = 0.f;
#pragma unroll
    for (int i = 0; i < D / 4; i++) {
        float4 av = a[i];
        float4 pv = p[i];
        asq += av.x * av.x + av.y * av.y + av.z * av.z + av.w * av.w;
        psq += pv.x * pv.x + pv.y * pv.y + pv.z * pv.z + pv.w * pv.w;
        float dx = av.x - pv.x, dy = av.y - pv.y, dz = av.z - pv.z, dw = av.w - pv.w;
        pd += dx * dx + dy * dy + dz * dz + dw * dw;
    }
    g_a_sq[row]     = asq;
    g_p_sq[row]     = psq;
    g_pos_d2[row]   = pd;
    g_neg_bits[row] = 0x7F800000u;  // +inf
}

// ---------------------------------------------------------------------------
// Kernel 2: fused tiled "GEMM + row-min of d2" over 128x128 tiles
// 256 threads, each computes an 8x8 micro-tile in 2x2 blocked layout:
//   rows:  ty*4+{0..3}  and  64+ty*4+{0..3}
//   cols:  tx*4+{0..3}  and  64+tx*4+{0..3}
// ---------------------------------------------------------------------------
__global__ __launch_bounds__(256)
void gemm_min_kernel(const float* __restrict__ feats) {
    const float* __restrict__ A = feats;                      // anchor  [BS][D]
    const float* __restrict__ P = feats + (size_t)BS * D;     // positive[BS][D]

    __shared__ float As[KC][TILE + 4];
    __shared__ float Ps[KC][TILE + 4];

    const int m0 = blockIdx.y * TILE;
    const int n0 = blockIdx.x * TILE;
    const int tid = threadIdx.x;
    const int tx = tid & 15;   // 0..15
    const int ty = tid >> 4;   // 0..15

    float acc[8][8];
#pragma unroll
    for (int i = 0; i < 8; i++)
#pragma unroll
        for (int j = 0; j < 8; j++) acc[i][j] = 0.f;

    for (int kc = 0; kc < D; kc += KC) {
        // Load 128 rows x 32 k of both tiles: 1024 float4 per array, 4/thread
#pragma unroll
        for (int j = 0; j < 4; j++) {
            int f   = tid + j * 256;       // 0..1023
            int row = f >> 3;              // 8 float4 per row (KC=32)
            int k4  = f & 7;
            float4 v = *(const float4*)(A + (size_t)(m0 + row) * D + kc + k4 * 4);
            As[k4 * 4 + 0][row] = v.x;
            As[k4 * 4 + 1][row] = v.y;
            As[k4 * 4 + 2][row] = v.z;
            As[k4 * 4 + 3][row] = v.w;
            float4 w = *(const float4*)(P + (size_t)(n0 + row) * D + kc + k4 * 4);
            Ps[k4 * 4 + 0][row] = w.x;
            Ps[k4 * 4 + 1][row] = w.y;
            Ps[k4 * 4 + 2][row] = w.z;
            Ps[k4 * 4 + 3][row] = w.w;
        }
        __syncthreads();

#pragma unroll
        for (int k = 0; k < KC; k++) {
            float4 a0 = *(const float4*)&As[k][ty * 4];
            float4 a1 = *(const float4*)&As[k][64 + ty * 4];
            float4 b0 = *(const float4*)&Ps[k][tx * 4];
            float4 b1 = *(const float4*)&Ps[k][64 + tx * 4];
            float af[8] = {a0.x, a0.y, a0.z, a0.w, a1.x, a1.y, a1.z, a1.w};
            float bf[8] = {b0.x, b0.y, b0.z, b0.w, b1.x, b1.y, b1.z, b1.w};
#pragma unroll
            for (int i = 0; i < 8; i++)
#pragma unroll
                for (int j = 0; j < 8; j++)
                    acc[i][j] = fmaf(af[i], bf[j], acc[i][j]);
        }
        __syncthreads();
    }

    // Epilogue: d2 = a_sq + p_sq - 2*cross ; row-min ; atomicMin into global
    int cols[8], rows[8];
#pragma unroll
    for (int j = 0; j < 4; j++) {
        cols[j]     = tx * 4 + j;
        cols[j + 4] = 64 + tx * 4 + j;
        rows[j]     = ty * 4 + j;
        rows[j + 4] = 64 + ty * 4 + j;
    }
    float psq[8];
#pragma unroll
    for (int j = 0; j < 8; j++) psq[j] = g_p_sq[n0 + cols[j]];

#pragma unroll
    for (int i = 0; i < 8; i++) {
        float asq = g_a_sq[m0 + rows[i]];
        float mn = CUDART_INF_F;
#pragma unroll
        for (int j = 0; j < 8; j++) {
            float d2 = asq + psq[j] - 2.0f * acc[i][j];
            mn = fminf(mn, d2);
        }
        // reduce across the 16 tx lanes (they share the same ty / rows)
#pragma unroll
        for (int off = 8; off > 0; off >>= 1)
            mn = fminf(mn, __shfl_xor_sync(0xffffffffu, mn, off, 16));
        if (tx == 0) {
            unsigned int bits = __float_as_uint(fmaxf(mn, 0.0f));
            atomicMin(&g_neg_bits[m0 + rows[i]], bits);
        }
    }
}

// ---------------------------------------------------------------------------
// Kernel 3: loss = mean(relu(sqrt(pos_d2) - sqrt(neg_d2) + 1))
// ---------------------------------------------------------------------------
__global__ void loss_kernel(float* __restrict__ out) {
    __shared__ float red[256];
    float sum = 0.f;
    for (int i = threadIdx.x; i < BS; i += 256) {
        float pos = sqrtf(g_pos_d2[i]);
        float neg = sqrtf(__uint_as_float(g_neg_bits[i]));  // already clamped >= 0
        sum += fmaxf(pos - neg + 1.0f, 0.0f);
    }
    red[threadIdx.x] = sum;
    __syncthreads();
    for (int s = 128; s > 0; s >>= 1) {
        if (threadIdx.x < s) red[threadIdx.x] += red[threadIdx.x + s];
        __syncthreads();
    }
    if (threadIdx.x == 0) out[0] = red[0] / (float)BS;
}

// ---------------------------------------------------------------------------
extern "C" void kernel_launch(void* const* d_in, const int* in_sizes, int n_in,
                              void* d_out, int out_size) {
    const float* feats = (const float*)d_in[0];
    float* out = (float*)d_out;

    prep_kernel<<<BS / 256, 256>>>(feats);

    dim3 grid(BS / TILE, BS / TILE);  // 64 x 64
    gemm_min_kernel<<<grid, 256>>>(feats);

    loss_kernel<<<1, 256>>>(out);
}

// round 12
// speedup vs baseline: 3.0726x; 3.0726x over previous
#include <cuda_runtime.h>
#include <cuda_bf16.h>
#include <math_constants.h>
#include <cstdint>

#define BS   8192
#define D    128
#define KK   256          // hi|lo concatenated K
#define NTILES 16         // n-tiles per CTA

// ---------------------------------------------------------------------------
// Scratch (__device__ globals — allocation-free rule)
// ---------------------------------------------------------------------------
__device__ float         g_a_sq[BS];
__device__ float         g_p_sq[BS];
__device__ float         g_pos_d2[BS];
__device__ unsigned int  g_neg_bits[BS];
// bf16 split of feats: [row][0:128] = hi, [row][128:256] = lo   (8 MB)
__device__ __nv_bfloat16 g_split[(size_t)2 * BS * KK];

// ---------------------------------------------------------------------------
// Helpers (baseline PTX only: sm_80-era instructions, valid on sm_103 base)
// ---------------------------------------------------------------------------
__device__ __forceinline__ uint32_t smem_u32(const void* p) {
    uint32_t a;
    asm("{ .reg .u64 t; cvta.to.shared.u64 t, %1; cvt.u32.u64 %0, t; }" : "=r"(a) : "l"(p));
    return a;
}

#define LDSM4(r0, r1, r2, r3, addr)                                          \
    asm volatile("ldmatrix.sync.aligned.m8n8.x4.shared.b16 {%0,%1,%2,%3}, [%4];" \
        : "=r"(r0), "=r"(r1), "=r"(r2), "=r"(r3) : "r"(addr))

#define MMA16816(ac, a, b0, b1)                                              \
    asm volatile("mma.sync.aligned.m16n8k16.row.col.f32.bf16.bf16.f32 "      \
        "{%0,%1,%2,%3}, {%4,%5,%6,%7}, {%8,%9}, {%0,%1,%2,%3};"              \
        : "+f"((ac)[0]), "+f"((ac)[1]), "+f"((ac)[2]), "+f"((ac)[3])         \
        : "r"((a)[0]), "r"((a)[1]), "r"((a)[2]), "r"((a)[3]),                \
          "r"(b0), "r"(b1))

#define CP_ASYNC16(dst_u32, src_ptr)                                         \
    asm volatile("cp.async.cg.shared.global [%0], [%1], 16;"                 \
        :: "r"(dst_u32), "l"(src_ptr))
#define CP_COMMIT()  asm volatile("cp.async.commit_group;" ::: "memory")
#define CP_WAIT0()   asm volatile("cp.async.wait_group 0;" ::: "memory")

// ---------------------------------------------------------------------------
// Kernel 1: norms + pos dist + neg init + bf16 hi/lo split. 4 threads/row.
// ---------------------------------------------------------------------------
__global__ __launch_bounds__(256) void prep_kernel(const float* __restrict__ feats) {
    int gid = blockIdx.x * 256 + threadIdx.x;
    int r = gid >> 2, s = gid & 3;
    if (r >= BS) return;

    const float4* a = (const float4*)(feats + (size_t)r * D) + s * 8;
    const float4* p = (const float4*)(feats + (size_t)(BS + r) * D) + s * 8;
    __nv_bfloat162* ah = (__nv_bfloat162*)(g_split + (size_t)r * KK + s * 32);
    __nv_bfloat162* al = (__nv_bfloat162*)(g_split + (size_t)r * KK + 128 + s * 32);
    __nv_bfloat162* ph = (__nv_bfloat162*)(g_split + (size_t)(BS + r) * KK + s * 32);
    __nv_bfloat162* pl = (__nv_bfloat162*)(g_split + (size_t)(BS + r) * KK + 128 + s * 32);

    float asq = 0.f, psq = 0.f, pd = 0.f;
#pragma unroll
    for (int i = 0; i < 8; i++) {
        float4 av = a[i], pv = p[i];
        asq += av.x * av.x + av.y * av.y + av.z * av.z + av.w * av.w;
        psq += pv.x * pv.x + pv.y * pv.y + pv.z * pv.z + pv.w * pv.w;
        float dx = av.x - pv.x, dy = av.y - pv.y, dz = av.z - pv.z, dw = av.w - pv.w;
        pd += dx * dx + dy * dy + dz * dz + dw * dw;

        __nv_bfloat16 hx = __float2bfloat16(av.x), hy = __float2bfloat16(av.y);
        __nv_bfloat16 hz = __float2bfloat16(av.z), hw = __float2bfloat16(av.w);
        ah[i * 2 + 0] = __nv_bfloat162(hx, hy);
        ah[i * 2 + 1] = __nv_bfloat162(hz, hw);
        al[i * 2 + 0] = __nv_bfloat162(__float2bfloat16(av.x - __bfloat162float(hx)),
                                       __float2bfloat16(av.y - __bfloat162float(hy)));
        al[i * 2 + 1] = __nv_bfloat162(__float2bfloat16(av.z - __bfloat162float(hz)),
                                       __float2bfloat16(av.w - __bfloat162float(hw)));

        hx = __float2bfloat16(pv.x); hy = __float2bfloat16(pv.y);
        hz = __float2bfloat16(pv.z); hw = __float2bfloat16(pv.w);
        ph[i * 2 + 0] = __nv_bfloat162(hx, hy);
        ph[i * 2 + 1] = __nv_bfloat162(hz, hw);
        pl[i * 2 + 0] = __nv_bfloat162(__float2bfloat16(pv.x - __bfloat162float(hx)),
                                       __float2bfloat16(pv.y - __bfloat162float(hy)));
        pl[i * 2 + 1] = __nv_bfloat162(__float2bfloat16(pv.z - __bfloat162float(hz)),
                                       __float2bfloat16(pv.w - __bfloat162float(hw)));
    }
#pragma unroll
    for (int off = 1; off < 4; off <<= 1) {
        asq += __shfl_xor_sync(0xffffffffu, asq, off);
        psq += __shfl_xor_sync(0xffffffffu, psq, off);
        pd  += __shfl_xor_sync(0xffffffffu, pd,  off);
    }
    if (s == 0) {
        g_a_sq[r] = asq;
        g_p_sq[r] = psq;
        g_pos_d2[r] = pd;
        g_neg_bits[r] = 0x7F800000u;
    }
}

// ---------------------------------------------------------------------------
// Kernel 2: HMMA (mma.sync bf16) GEMM, K=256 (hi|lo), fused row-min epilogue
//   grid (4, 64): blockIdx.y = m-tile (128 rows), blockIdx.x = group of 16
//   n-tiles. Per CTA: A tile resident, B double-buffered via cp.async.
//   Smem rows: 256 bf16 = 512 B = 32 chunks of 16 B, xor-swizzled:
//     phys_chunk = (c & 24) | ((c ^ row) & 7)
// ---------------------------------------------------------------------------
#define SM_PSQ 0                       // 2 x 128 floats = 1024 B
#define SM_A   1024                    // 65536 B
#define SM_B0  (SM_A + 65536)
#define SM_B1  (SM_B0 + 65536)
#define SMEM_TOTAL (SM_B1 + 65536)     // 197632 B

__device__ __forceinline__ void load_tile_async(char* dst, const __nv_bfloat16* src,
                                                int tid) {
    const char* s8 = (const char*)src;
#pragma unroll
    for (int p = 0; p < 16; p++) {
        int idx = tid + p * 256;          // 0..4095
        int row = idx >> 5;               // 0..127
        int c   = idx & 31;               // 16B chunk
        int cs  = (c & 24) | ((c ^ row) & 7);
        uint32_t d = smem_u32(dst + row * 512 + cs * 16);
        CP_ASYNC16(d, s8 + (size_t)row * 512 + c * 16);
    }
}

__global__ __launch_bounds__(256, 1) void gemm_min_kernel() {
    extern __shared__ __align__(128) char smem[];
    float* psq_s = (float*)(smem + SM_PSQ);

    const int tid  = threadIdx.x;
    const int lane = tid & 31, wid = tid >> 5;
    const int wm = wid >> 2;              // 0..1  (m: 64 rows each)
    const int wn = wid & 3;               // 0..3  (n: 32 cols each)
    const int g = lane >> 2, t = lane & 3;
    const int m0  = blockIdx.y * 128;
    const int nt0 = blockIdx.x * NTILES;

    // initial loads: A tile + B tile 0 + psq 0
    load_tile_async(smem + SM_A, g_split + (size_t)m0 * KK, tid);
    load_tile_async(smem + SM_B0, g_split + (size_t)(BS + nt0 * 128) * KK, tid);
    if (tid < 128) psq_s[tid] = g_p_sq[nt0 * 128 + tid];
    CP_COMMIT();
    CP_WAIT0();
    __syncthreads();

    // precomputed ldmatrix row indices (constant over ks / tiles)
    // A: 4 m-frags of 16 rows; B: 2 n-pairs of 16 rows
    int rowA[4], rowB[2];
#pragma unroll
    for (int mi = 0; mi < 4; mi++) rowA[mi] = wm * 64 + mi * 16 + (lane & 15);
#pragma unroll
    for (int pi = 0; pi < 2; pi++)
        rowB[pi] = wn * 32 + pi * 16 + ((lane >> 4) & 1) * 8 + (lane & 7);
    const int chA_add = (lane >> 4);        // 0/1: k chunk within k-step
    const int chB_add = ((lane >> 3) & 1);

    float rm[8];
#pragma unroll
    for (int i = 0; i < 8; i++) rm[i] = CUDART_INF_F;

    for (int it = 0; it < NTILES; it++) {
        char* Bc = smem + ((it & 1) ? SM_B1 : SM_B0);
        const int nxt = (it + 1) & 1;
        if (it + 1 < NTILES) {
            load_tile_async(smem + (nxt ? SM_B1 : SM_B0),
                            g_split + (size_t)(BS + (nt0 + it + 1) * 128) * KK, tid);
            if (tid < 128)
                psq_s[nxt * 128 + tid] = g_p_sq[(nt0 + it + 1) * 128 + tid];
            CP_COMMIT();
        }

        float acc[4][4][4];
#pragma unroll
        for (int mi = 0; mi < 4; mi++)
#pragma unroll
            for (int ni = 0; ni < 4; ni++)
#pragma unroll
                for (int e = 0; e < 4; e++) acc[mi][ni][e] = 0.f;

#pragma unroll
        for (int ks = 0; ks < KK / 16; ks++) {
            uint32_t a[4][4];
#pragma unroll
            for (int mi = 0; mi < 4; mi++) {
                int r = rowA[mi];
                int c = ks * 2 + chA_add;
                int cs = (c & 24) | ((c ^ r) & 7);
                uint32_t ad = smem_u32(smem + SM_A + r * 512 + cs * 16);
                LDSM4(a[mi][0], a[mi][1], a[mi][2], a[mi][3], ad);
            }
            uint32_t b[2][4];
#pragma unroll
            for (int pi = 0; pi < 2; pi++) {
                int r = rowB[pi];
                int c = ks * 2 + chB_add;
                int cs = (c & 24) | ((c ^ r) & 7);
                uint32_t bd = smem_u32(Bc + r * 512 + cs * 16);
                LDSM4(b[pi][0], b[pi][1], b[pi][2], b[pi][3], bd);
            }
#pragma unroll
            for (int mi = 0; mi < 4; mi++) {
#pragma unroll
                for (int ni = 0; ni < 4; ni++) {
                    uint32_t b0 = b[ni >> 1][(ni & 1) * 2 + 0];
                    uint32_t b1 = b[ni >> 1][(ni & 1) * 2 + 1];
                    MMA16816(acc[mi][ni], a[mi], b0, b1);
                }
            }
        }

        // fold min(p_sq - 2*cross) into running mins
        const float* ps = psq_s + (it & 1) * 128;
#pragma unroll
        for (int mi = 0; mi < 4; mi++) {
#pragma unroll
            for (int ni = 0; ni < 4; ni++) {
                int cb = wn * 32 + ni * 8 + 2 * t;
                float p0 = ps[cb], p1 = ps[cb + 1];
                rm[mi * 2 + 0] = fminf(rm[mi * 2 + 0],
                                       fminf(p0 - 2.f * acc[mi][ni][0],
                                             p1 - 2.f * acc[mi][ni][1]));
                rm[mi * 2 + 1] = fminf(rm[mi * 2 + 1],
                                       fminf(p0 - 2.f * acc[mi][ni][2],
                                             p1 - 2.f * acc[mi][ni][3]));
            }
        }

        if (it + 1 < NTILES) CP_WAIT0();
        __syncthreads();
    }

    // reduce across the 4 lanes sharing each row (t = 0..3), then atomicMin
#pragma unroll
    for (int k = 0; k < 8; k++) {
        float v = rm[k];
        v = fminf(v, __shfl_xor_sync(0xffffffffu, v, 1));
        v = fminf(v, __shfl_xor_sync(0xffffffffu, v, 2));
        if (t == 0) {
            int mi = k >> 1, h = k & 1;
            int row = m0 + wm * 64 + mi * 16 + h * 8 + g;
            float d2 = fmaxf(g_a_sq[row] + v, 0.0f);
            atomicMin(&g_neg_bits[row], __float_as_uint(d2));
        }
    }
}

// ---------------------------------------------------------------------------
// Kernel 3: loss = mean(relu(sqrt(pos_d2) - sqrt(neg_d2) + 1))
// ---------------------------------------------------------------------------
__global__ void loss_kernel(float* __restrict__ out) {
    __shared__ float red[1024];
    float sum = 0.f;
    for (int i = threadIdx.x; i < BS; i += 1024) {
        float pos = sqrtf(g_pos_d2[i]);
        float neg = sqrtf(__uint_as_float(g_neg_bits[i]));
        sum += fmaxf(pos - neg + 1.0f, 0.0f);
    }
    red[threadIdx.x] = sum;
    __syncthreads();
    for (int s = 512; s > 0; s >>= 1) {
        if (threadIdx.x < s) red[threadIdx.x] += red[threadIdx.x + s];
        __syncthreads();
    }
    if (threadIdx.x == 0) out[0] = red[0] / (float)BS;
}

// ---------------------------------------------------------------------------
extern "C" void kernel_launch(void* const* d_in, const int* in_sizes, int n_in,
                              void* d_out, int out_size) {
    const float* feats = (const float*)d_in[0];
    float* out = (float*)d_out;

    cudaFuncSetAttribute(gemm_min_kernel,
                         cudaFuncAttributeMaxDynamicSharedMemorySize, SMEM_TOTAL);

    prep_kernel<<<BS * 4 / 256, 256>>>(feats);
    gemm_min_kernel<<<dim3(4, 64), 256, SMEM_TOTAL>>>();
    loss_kernel<<<1, 1024>>>(out);
}

// round 16
// speedup vs baseline: 3.4037x; 1.1078x over previous
#include <cuda_runtime.h>
#include <cuda_bf16.h>
#include <math_constants.h>
#include <cstdint>

#define BS   8192
#define D    128
#define KK   256          // hi|lo concatenated K
#define NTILES 32         // n-tiles per CTA (grid.x = 2 -> single wave)

// ---------------------------------------------------------------------------
// Scratch (__device__ globals — allocation-free rule)
// ---------------------------------------------------------------------------
__device__ float         g_a_sq[BS];
__device__ float         g_p_sq[BS];
__device__ float         g_pos_d2[BS];
__device__ unsigned int  g_neg_bits[BS];
// bf16 split of feats: [row][0:128] = hi, [row][128:256] = lo   (8 MB)
__device__ __nv_bfloat16 g_split[(size_t)2 * BS * KK];

// ---------------------------------------------------------------------------
// Helpers (baseline PTX only: sm_80-era instructions, valid on sm_103 base)
// ---------------------------------------------------------------------------
__device__ __forceinline__ uint32_t smem_u32(const void* p) {
    uint32_t a;
    asm("{ .reg .u64 t; cvta.to.shared.u64 t, %1; cvt.u32.u64 %0, t; }" : "=r"(a) : "l"(p));
    return a;
}

#define LDSM4(r0, r1, r2, r3, addr)                                          \
    asm volatile("ldmatrix.sync.aligned.m8n8.x4.shared.b16 {%0,%1,%2,%3}, [%4];" \
        : "=r"(r0), "=r"(r1), "=r"(r2), "=r"(r3) : "r"(addr))

#define MMA16816(ac, a, b0, b1)                                              \
    asm volatile("mma.sync.aligned.m16n8k16.row.col.f32.bf16.bf16.f32 "      \
        "{%0,%1,%2,%3}, {%4,%5,%6,%7}, {%8,%9}, {%0,%1,%2,%3};"              \
        : "+f"((ac)[0]), "+f"((ac)[1]), "+f"((ac)[2]), "+f"((ac)[3])         \
        : "r"((a)[0]), "r"((a)[1]), "r"((a)[2]), "r"((a)[3]),                \
          "r"(b0), "r"(b1))

#define CP_ASYNC16(dst_u32, src_ptr)                                         \
    asm volatile("cp.async.cg.shared.global [%0], [%1], 16;"                 \
        :: "r"(dst_u32), "l"(src_ptr))
#define CP_COMMIT()  asm volatile("cp.async.commit_group;" ::: "memory")
#define CP_WAIT0()   asm volatile("cp.async.wait_group 0;" ::: "memory")

// ---------------------------------------------------------------------------
// Kernel 1: norms + pos dist + neg init + bf16 hi/lo split. 16 threads/row.
// Also zeroes out[0] (accumulated by loss_kernel via atomicAdd).
// ---------------------------------------------------------------------------
__global__ __launch_bounds__(256) void prep_kernel(const float* __restrict__ feats,
                                                   float* __restrict__ out) {
    int gid = blockIdx.x * 256 + threadIdx.x;
    int r = gid >> 4, s = gid & 15;       // row, 1/16 segment (8 floats)
    if (gid == 0) out[0] = 0.0f;
    if (r >= BS) return;

    const float4* a = (const float4*)(feats + (size_t)r * D) + s * 2;
    const float4* p = (const float4*)(feats + (size_t)(BS + r) * D) + s * 2;
    __nv_bfloat162* ah = (__nv_bfloat162*)(g_split + (size_t)r * KK + s * 8);
    __nv_bfloat162* al = (__nv_bfloat162*)(g_split + (size_t)r * KK + 128 + s * 8);
    __nv_bfloat162* ph = (__nv_bfloat162*)(g_split + (size_t)(BS + r) * KK + s * 8);
    __nv_bfloat162* pl = (__nv_bfloat162*)(g_split + (size_t)(BS + r) * KK + 128 + s * 8);

    float asq = 0.f, psq = 0.f, pd = 0.f;
#pragma unroll
    for (int i = 0; i < 2; i++) {
        float4 av = a[i], pv = p[i];
        asq += av.x * av.x + av.y * av.y + av.z * av.z + av.w * av.w;
        psq += pv.x * pv.x + pv.y * pv.y + pv.z * pv.z + pv.w * pv.w;
        float dx = av.x - pv.x, dy = av.y - pv.y, dz = av.z - pv.z, dw = av.w - pv.w;
        pd += dx * dx + dy * dy + dz * dz + dw * dw;

        __nv_bfloat16 hx = __float2bfloat16(av.x), hy = __float2bfloat16(av.y);
        __nv_bfloat16 hz = __float2bfloat16(av.z), hw = __float2bfloat16(av.w);
        ah[i * 2 + 0] = __nv_bfloat162(hx, hy);
        ah[i * 2 + 1] = __nv_bfloat162(hz, hw);
        al[i * 2 + 0] = __nv_bfloat162(__float2bfloat16(av.x - __bfloat162float(hx)),
                                       __float2bfloat16(av.y - __bfloat162float(hy)));
        al[i * 2 + 1] = __nv_bfloat162(__float2bfloat16(av.z - __bfloat162float(hz)),
                                       __float2bfloat16(av.w - __bfloat162float(hw)));

        hx = __float2bfloat16(pv.x); hy = __float2bfloat16(pv.y);
        hz = __float2bfloat16(pv.z); hw = __float2bfloat16(pv.w);
        ph[i * 2 + 0] = __nv_bfloat162(hx, hy);
        ph[i * 2 + 1] = __nv_bfloat162(hz, hw);
        pl[i * 2 + 0] = __nv_bfloat162(__float2bfloat16(pv.x - __bfloat162float(hx)),
                                       __float2bfloat16(pv.y - __bfloat162float(hy)));
        pl[i * 2 + 1] = __nv_bfloat162(__float2bfloat16(pv.z - __bfloat162float(hz)),
                                       __float2bfloat16(pv.w - __bfloat162float(hw)));
    }
#pragma unroll
    for (int off = 1; off < 16; off <<= 1) {
        asq += __shfl_xor_sync(0xffffffffu, asq, off);
        psq += __shfl_xor_sync(0xffffffffu, psq, off);
        pd  += __shfl_xor_sync(0xffffffffu, pd,  off);
    }
    if (s == 0) {
        g_a_sq[r] = asq;
        g_p_sq[r] = psq;
        g_pos_d2[r] = pd;
        g_neg_bits[r] = 0x7F800000u;
    }
}

// ---------------------------------------------------------------------------
// Kernel 2: HMMA (mma.sync bf16) GEMM, K=256 (hi|lo), fused row-min epilogue
//   grid (2, 64): blockIdx.y = m-tile (128 rows), blockIdx.x = group of 32
//   n-tiles -> 128 CTAs, single wave on 148 SMs.
//   Smem rows: 256 bf16 = 512 B = 32 chunks of 16 B, xor-swizzled:
//     phys_chunk = (c & 24) | ((c ^ row) & 7)
// ---------------------------------------------------------------------------
#define SM_PSQ 0                       // 2 x 128 floats = 1024 B
#define SM_A   1024                    // 65536 B
#define SM_B0  (SM_A + 65536)
#define SM_B1  (SM_B0 + 65536)
#define SMEM_TOTAL (SM_B1 + 65536)     // 197632 B

__device__ __forceinline__ void load_tile_async(char* dst, const __nv_bfloat16* src,
                                                int tid) {
    const char* s8 = (const char*)src;
#pragma unroll
    for (int p = 0; p < 16; p++) {
        int idx = tid + p * 256;          // 0..4095
        int row = idx >> 5;               // 0..127
        int c   = idx & 31;               // 16B chunk
        int cs  = (c & 24) | ((c ^ row) & 7);
        uint32_t d = smem_u32(dst + row * 512 + cs * 16);
        CP_ASYNC16(d, s8 + (size_t)row * 512 + c * 16);
    }
}

__global__ __launch_bounds__(256, 1) void gemm_min_kernel() {
    extern __shared__ __align__(128) char smem[];
    float* psq_s = (float*)(smem + SM_PSQ);

    const int tid  = threadIdx.x;
    const int lane = tid & 31, wid = tid >> 5;
    const int wm = wid >> 2;              // 0..1  (m: 64 rows each)
    const int wn = wid & 3;               // 0..3  (n: 32 cols each)
    const int g = lane >> 2, t = lane & 3;
    const int m0  = blockIdx.y * 128;
    const int nt0 = blockIdx.x * NTILES;

    // initial loads: A tile + B tile 0 + psq 0
    load_tile_async(smem + SM_A, g_split + (size_t)m0 * KK, tid);
    load_tile_async(smem + SM_B0, g_split + (size_t)(BS + nt0 * 128) * KK, tid);
    if (tid < 128) psq_s[tid] = g_p_sq[nt0 * 128 + tid];
    CP_COMMIT();
    CP_WAIT0();
    __syncthreads();

    // precomputed ldmatrix row indices (constant over ks / tiles)
    int rowA[4], rowB[2];
#pragma unroll
    for (int mi = 0; mi < 4; mi++) rowA[mi] = wm * 64 + mi * 16 + (lane & 15);
#pragma unroll
    for (int pi = 0; pi < 2; pi++)
        rowB[pi] = wn * 32 + pi * 16 + ((lane >> 4) & 1) * 8 + (lane & 7);
    const int chA_add = (lane >> 4);
    const int chB_add = ((lane >> 3) & 1);

    float rm[8];
#pragma unroll
    for (int i = 0; i < 8; i++) rm[i] = CUDART_INF_F;

    for (int it = 0; it < NTILES; it++) {
        char* Bc = smem + ((it & 1) ? SM_B1 : SM_B0);
        const int nxt = (it + 1) & 1;
        if (it + 1 < NTILES) {
            load_tile_async(smem + (nxt ? SM_B1 : SM_B0),
                            g_split + (size_t)(BS + (nt0 + it + 1) * 128) * KK, tid);
            if (tid < 128)
                psq_s[nxt * 128 + tid] = g_p_sq[(nt0 + it + 1) * 128 + tid];
            CP_COMMIT();
        }

        float acc[4][4][4];
#pragma unroll
        for (int mi = 0; mi < 4; mi++)
#pragma unroll
            for (int ni = 0; ni < 4; ni++)
#pragma unroll
                for (int e = 0; e < 4; e++) acc[mi][ni][e] = 0.f;

#pragma unroll
        for (int ks = 0; ks < KK / 16; ks++) {
            uint32_t a[4][4];
#pragma unroll
            for (int mi = 0; mi < 4; mi++) {
                int r = rowA[mi];
                int c = ks * 2 + chA_add;
                int cs = (c & 24) | ((c ^ r) & 7);
                uint32_t ad = smem_u32(smem + SM_A + r * 512 + cs * 16);
                LDSM4(a[mi][0], a[mi][1], a[mi][2], a[mi][3], ad);
            }
            uint32_t b[2][4];
#pragma unroll
            for (int pi = 0; pi < 2; pi++) {
                int r = rowB[pi];
                int c = ks * 2 + chB_add;
                int cs = (c & 24) | ((c ^ r) & 7);
                uint32_t bd = smem_u32(Bc + r * 512 + cs * 16);
                LDSM4(b[pi][0], b[pi][1], b[pi][2], b[pi][3], bd);
            }
#pragma unroll
            for (int mi = 0; mi < 4; mi++) {
#pragma unroll
                for (int ni = 0; ni < 4; ni++) {
                    uint32_t b0 = b[ni >> 1][(ni & 1) * 2 + 0];
                    uint32_t b1 = b[ni >> 1][(ni & 1) * 2 + 1];
                    MMA16816(acc[mi][ni], a[mi], b0, b1);
                }
            }
        }

        // fold min(p_sq - 2*cross) into running mins
        const float* ps = psq_s + (it & 1) * 128;
#pragma unroll
        for (int mi = 0; mi < 4; mi++) {
#pragma unroll
            for (int ni = 0; ni < 4; ni++) {
                int cb = wn * 32 + ni * 8 + 2 * t;
                float p0 = ps[cb], p1 = ps[cb + 1];
                rm[mi * 2 + 0] = fminf(rm[mi * 2 + 0],
                                       fminf(p0 - 2.f * acc[mi][ni][0],
                                             p1 - 2.f * acc[mi][ni][1]));
                rm[mi * 2 + 1] = fminf(rm[mi * 2 + 1],
                                       fminf(p0 - 2.f * acc[mi][ni][2],
                                             p1 - 2.f * acc[mi][ni][3]));
            }
        }

        if (it + 1 < NTILES) CP_WAIT0();
        __syncthreads();
    }

    // reduce across the 4 lanes sharing each row, then atomicMin
#pragma unroll
    for (int k = 0; k < 8; k++) {
        float v = rm[k];
        v = fminf(v, __shfl_xor_sync(0xffffffffu, v, 1));
        v = fminf(v, __shfl_xor_sync(0xffffffffu, v, 2));
        if (t == 0) {
            int mi = k >> 1, h = k & 1;
            int row = m0 + wm * 64 + mi * 16 + h * 8 + g;
            float d2 = fmaxf(g_a_sq[row] + v, 0.0f);
            atomicMin(&g_neg_bits[row], __float_as_uint(d2));
        }
    }
}

// ---------------------------------------------------------------------------
// Kernel 3: loss — 32 blocks, block-reduce + one atomicAdd each.
// out[0] was zeroed by prep_kernel; graph stream order guarantees sequencing.
// ---------------------------------------------------------------------------
__global__ __launch_bounds__(256) void loss_kernel(float* __restrict__ out) {
    __shared__ float red[256];
    int i = blockIdx.x * 256 + threadIdx.x;   // 32*256 = 8192 exactly
    float pos = sqrtf(g_pos_d2[i]);
    float neg = sqrtf(__uint_as_float(g_neg_bits[i]));
    float v = fmaxf(pos - neg + 1.0f, 0.0f);
#pragma unroll
    for (int off = 16; off > 0; off >>= 1)
        v += __shfl_xor_sync(0xffffffffu, v, off);
    if ((threadIdx.x & 31) == 0) red[threadIdx.x >> 5] = v;
    __syncthreads();
    if (threadIdx.x < 8) {
        float s = red[threadIdx.x];
#pragma unroll
        for (int off = 4; off > 0; off >>= 1)
            s += __shfl_xor_sync(0xffu, s, off);
        if (threadIdx.x == 0) atomicAdd(out, s * (1.0f / (float)BS));
    }
}

// ---------------------------------------------------------------------------
extern "C" void kernel_launch(void* const* d_in, const int* in_sizes, int n_in,
                              void* d_out, int out_size) {
    const float* feats = (const float*)d_in[0];
    float* out = (float*)d_out;

    cudaFuncSetAttribute(gemm_min_kernel,
                         cudaFuncAttributeMaxDynamicSharedMemorySize, SMEM_TOTAL);

    prep_kernel<<<BS * 16 / 256, 256>>>(feats, out);   // 512 blocks
    gemm_min_kernel<<<dim3(2, 64), 256, SMEM_TOTAL>>>();
    loss_kernel<<<32, 256>>>(out);
}